// round 3
// baseline (speedup 1.0000x reference)
#include <cuda_runtime.h>

#define Wd 256
#define Hd 256
#define Bd 64
#define NPIX (Bd*Hd*Wd)
#define NV   (NPIX/4)
#define EPSf 1e-12f

#define TX 64
#define TY 16
#define USTR 72   // u smem row stride; 18 rows (ty-1..ty+16), cols -4..67
#define PSTR 68   // p smem row stride; 17 rows (ty-1..ty+15), cols -4..63

// ---- iteration-invariant scratch ----
__device__ __align__(16) float g_g2x[NPIX];
__device__ __align__(16) float g_g2y[NPIX];
__device__ __align__(16) float g_rc [NPIX];
// ---- double-buffered dual state ----
__device__ __align__(16) float g_p11[2][NPIX];
__device__ __align__(16) float g_p12[2][NPIX];
__device__ __align__(16) float g_p21[2][NPIX];
__device__ __align__(16) float g_p22[2][NPIX];
// ---- u scratch (ping-pongs with d_out) ----
__device__ __align__(16) float g_u1s[NPIX];
__device__ __align__(16) float g_u2s[NPIX];

union F4 { float4 v; float f[4]; };

__device__ __forceinline__ float4 ld4(const float* p) { return *reinterpret_cast<const float4*>(p); }
__device__ __forceinline__ void   st4(float* p, float4 v) { *reinterpret_cast<float4*>(p) = v; }

// ============================================================================
// Init: g2x, g2y, rc = y - x, and the iteration-1 u-update (u=0, p=0).
// ============================================================================
__global__ void __launch_bounds__(256) k_init(
    const float* __restrict__ x, const float* __restrict__ y,
    const float* __restrict__ tp, const float* __restrict__ lp,
    float* __restrict__ u1, float* __restrict__ u2)
{
    int v = blockIdx.x * blockDim.x + threadIdx.x;
    if (v >= NV) return;
    int idx = v << 2;
    int j4 = idx & (Wd - 1);
    int i  = (idx >> 8) & (Hd - 1);

    float ts  = tp[0];
    float l_t = lp[0] * ts;

    F4 X, Y, Yu, Yd, Xu, Xd;
    X.v = ld4(x + idx);
    Y.v = ld4(y + idx);
    float yl = (j4 > 0)       ? y[idx - 1] : 0.f;
    float yr = (j4 + 4 < Wd)  ? y[idx + 4] : 0.f;
    Yu.v = (i > 0)      ? ld4(y + idx - Wd) : make_float4(0,0,0,0);
    Yd.v = (i < Hd - 1) ? ld4(y + idx + Wd) : make_float4(0,0,0,0);
    Xd.v = (i == 0)      ? ld4(x + idx + Wd) : make_float4(0,0,0,0);
    Xu.v = (i == Hd - 1) ? ld4(x + idx - Wd) : make_float4(0,0,0,0);

    F4 GX, GY, RC, O1, O2;
#pragma unroll
    for (int k = 0; k < 4; k++) {
        int j = j4 + k;
        float gx;
        if (j == 0)            gx = 0.5f * (X.f[1] - X.f[0]);
        else if (j == Wd - 1)  gx = 0.5f * (X.f[3] - X.f[2]);
        else {
            float yn = (k < 3) ? Y.f[k + 1] : yr;
            float yp = (k > 0) ? Y.f[k - 1] : yl;
            gx = 0.5f * (yn - yp);
        }
        float gy;
        if (i == 0)            gy = 0.5f * (Xd.f[k] - X.f[k]);
        else if (i == Hd - 1)  gy = 0.5f * (X.f[k] - Xu.f[k]);
        else                   gy = 0.5f * (Yd.f[k] - Yu.f[k]);

        float rc = Y.f[k] - X.f[k];
        GX.f[k] = gx; GY.f[k] = gy; RC.f[k] = rc;

        float rho  = rc + EPSf;
        float grad = gx * gx + gy * gy + EPSf;
        float lg   = l_t * grad;
        float v1, v2;
        if      (rho < -lg)   { v1 =  l_t * gx; v2 =  l_t * gy; }
        else if (rho >  lg)   { v1 = -l_t * gx; v2 = -l_t * gy; }
        else if (grad > EPSf) { float s = -rho / grad; v1 = s * gx; v2 = s * gy; }
        else                  { v1 = 0.f; v2 = 0.f; }
        O1.f[k] = v1; O2.f[k] = v2;
    }
    st4(g_g2x + idx, GX.v);
    st4(g_g2y + idx, GY.v);
    st4(g_rc  + idx, RC.v);
    st4(u1 + idx, O1.v);
    st4(u2 + idx, O2.v);
}

// ============================================================================
// Fused (P_k, U_{k+1}) with double-buffered state (no intra-launch races):
//  reads u from (u1r,u2r), p_old from p-set PRD; writes p_new to set PWR
//  (center only; skipped if LAST) and u_new to (u1w,u2w).
// ============================================================================
template<bool FIRST, bool LAST, int PRD, int PWR>
__global__ void __launch_bounds__(256) k_fused(
    const float* __restrict__ tp, const float* __restrict__ lp,
    const float* __restrict__ ap,
    const float* __restrict__ u1r, const float* __restrict__ u2r,
    float* __restrict__ u1w, float* __restrict__ u2w)
{
    __shared__ __align__(16) float sU1[18*USTR], sU2[18*USTR];
    __shared__ __align__(16) float sP11[17*PSTR], sP12[17*PSTR];
    __shared__ __align__(16) float sP21[17*PSTR], sP22[17*PSTR];

    const int tid = threadIdx.x;
    const int tx0 = blockIdx.x * TX;
    const int ty0 = blockIdx.y * TY;
    const size_t pbase = (size_t)blockIdx.z * (Hd * Wd);

    const float ts   = tp[0];
    const float l_t  = lp[0] * ts;
    const float taut = ap[0] / ts;

    // ---- stage 1: u tile (18 rows x 18 float4 cols) ----
    for (int t = tid; t < 18*18; t += 256) {
        int r = t / 18, v = t % 18;
        int gr = ty0 - 1 + r;
        int gj = tx0 - 4 + v * 4;
        float4 a = make_float4(0,0,0,0), b = a;
        if (gr >= 0 && gr < Hd && gj >= 0 && gj < Wd) {
            size_t o = pbase + (size_t)gr * Wd + gj;
            a = ld4(u1r + o);
            b = ld4(u2r + o);
        }
        st4(sU1 + r*USTR + v*4, a);
        st4(sU2 + r*USTR + v*4, b);
    }
    __syncthreads();

    // ---- stage 2: p update on extended region (17 rows x 17 float4 cols) ----
    for (int t = tid; t < 17*17; t += 256) {
        int pr = t / 17, pv = t % 17;
        int rloc  = pr - 1;          // -1..15
        int cbase = pv * 4 - 4;      // -4..60
        int grow = ty0 + rloc;
        int gcol = tx0 + cbase;
        bool inimg = (grow >= 0) && (gcol >= 0);

        int su = pr*USTR + pv*4;
        F4 U1c, U2c, U1d, U2d;
        U1c.v = *(float4*)(sU1 + su);
        U2c.v = *(float4*)(sU2 + su);
        U1d.v = *(float4*)(sU1 + su + USTR);
        U2d.v = *(float4*)(sU2 + su + USTR);
        float u1rr = sU1[su + 4];
        float u2rr = sU2[su + 4];

        F4 P11o, P12o, P21o, P22o;
        if (!FIRST && inimg) {
            size_t o = pbase + (size_t)grow * Wd + gcol;
            P11o.v = ld4(g_p11[PRD] + o);
            P12o.v = ld4(g_p12[PRD] + o);
            P21o.v = ld4(g_p21[PRD] + o);
            P22o.v = ld4(g_p22[PRD] + o);
        } else {
            P11o.v = P12o.v = P21o.v = P22o.v = make_float4(0,0,0,0);
        }

        bool hasd = (grow < Hd - 1);
        F4 O11, O12, O21, O22;
#pragma unroll
        for (int k = 0; k < 4; k++) {
            int j = gcol + k;
            float n1u = (k < 3) ? U1c.f[k+1] : u1rr;
            float n2u = (k < 3) ? U2c.f[k+1] : u2rr;
            float u1x = (j < Wd - 1) ? (n1u - U1c.f[k]) : 0.f;
            float u2x = (j < Wd - 1) ? (n2u - U2c.f[k]) : 0.f;
            float u1y = hasd ? (U1d.f[k] - U1c.f[k]) : 0.f;
            float u2y = hasd ? (U2d.f[k] - U2c.f[k]) : 0.f;

            float n1 = sqrtf(u1x*u1x + u1y*u1y + EPSf);
            float n2 = sqrtf(u2x*u2x + u2y*u2y + EPSf);
            float f1 = 1.0f / (1.0f + taut * n1);
            float f2 = 1.0f / (1.0f + taut * n2);

            O11.f[k] = (P11o.f[k] + taut * u1x) * f1;
            O12.f[k] = (P12o.f[k] + taut * u1y) * f1;
            O21.f[k] = (P21o.f[k] + taut * u2x) * f2;
            O22.f[k] = (P22o.f[k] + taut * u2y) * f2;
        }

        int sp = pr*PSTR + pv*4;
        st4(sP11 + sp, O11.v);
        st4(sP12 + sp, O12.v);
        st4(sP21 + sp, O21.v);
        st4(sP22 + sp, O22.v);

        if (!LAST && pr >= 1 && pv >= 1) {   // center tile only
            size_t o = pbase + (size_t)grow * Wd + gcol;
            st4(g_p11[PWR] + o, O11.v);
            st4(g_p12[PWR] + o, O12.v);
            st4(g_p21[PWR] + o, O21.v);
            st4(g_p22[PWR] + o, O22.v);
        }
    }
    __syncthreads();

    // ---- stage 3: u update on center tile ----
    {
        int r = tid >> 4;        // 0..15
        int v = tid & 15;        // 0..15
        int grow = ty0 + r;
        int gcol = tx0 + v*4;
        size_t o = pbase + (size_t)grow * Wd + gcol;

        F4 GX, GY, RC;
        GX.v = ld4(g_g2x + o);
        GY.v = ld4(g_g2y + o);
        RC.v = ld4(g_rc  + o);

        int su = (r+1)*USTR + v*4 + 4;
        F4 U1c, U2c;
        U1c.v = *(float4*)(sU1 + su);
        U2c.v = *(float4*)(sU2 + su);

        int sp = (r+1)*PSTR + v*4 + 4;
        F4 P11, P12, P21, P22, P12u, P22u;
        P11.v  = *(float4*)(sP11 + sp);
        P12.v  = *(float4*)(sP12 + sp);
        P21.v  = *(float4*)(sP21 + sp);
        P22.v  = *(float4*)(sP22 + sp);
        P12u.v = *(float4*)(sP12 + sp - PSTR);
        P22u.v = *(float4*)(sP22 + sp - PSTR);
        float p11l = sP11[sp - 1];
        float p21l = sP21[sp - 1];

        F4 O1, O2;
#pragma unroll
        for (int k = 0; k < 4; k++) {
            int j = gcol + k;
            float l11 = (k > 0) ? P11.f[k-1] : p11l;
            float l21 = (k > 0) ? P21.f[k-1] : p21l;
            float dx1 = (j == 0) ? P11.f[k] : (P11.f[k] - l11);
            float dx2 = (j == 0) ? P21.f[k] : (P21.f[k] - l21);
            float dy1 = (grow == 0) ? P12.f[k] : (P12.f[k] - P12u.f[k]);
            float dy2 = (grow == 0) ? P22.f[k] : (P22.f[k] - P22u.f[k]);

            float gx = GX.f[k], gy = GY.f[k];
            float rho  = RC.f[k] + gx * U1c.f[k] + gy * U2c.f[k] + EPSf;
            float grad = gx * gx + gy * gy + EPSf;
            float lg   = l_t * grad;
            float v1, v2;
            if      (rho < -lg)   { v1 =  l_t * gx; v2 =  l_t * gy; }
            else if (rho >  lg)   { v1 = -l_t * gx; v2 = -l_t * gy; }
            else if (grad > EPSf) { float s = -rho / grad; v1 = s * gx; v2 = s * gy; }
            else                  { v1 = 0.f; v2 = 0.f; }

            O1.f[k] = U1c.f[k] + v1 + ts * (dx1 + dy1);
            O2.f[k] = U2c.f[k] + v2 + ts * (dx2 + dy2);
        }
        st4(u1w + o, O1.v);
        st4(u2w + o, O2.v);
    }
}

// ============================================================================
// Launch: init(+U1) -> us; then 9 fused kernels ping-ponging u and p buffers.
// f1: us->ud (p w0), f2: ud->us (p r0 w1), f3: us->ud (p r1 w0), ...
// f9: us->ud (p r1, no write). d_out ends with U10.
// ============================================================================
extern "C" void kernel_launch(void* const* d_in, const int* in_sizes, int n_in,
                              void* d_out, int out_size)
{
    const float* x = (const float*)d_in[0];
    const float* y = (const float*)d_in[1];
    const float* t = (const float*)d_in[8];
    const float* l = (const float*)d_in[9];
    const float* a = (const float*)d_in[10];

    float* ud1 = (float*)d_out;
    float* ud2 = ud1 + NPIX;

    float* us1; cudaGetSymbolAddress((void**)&us1, g_u1s);
    float* us2; cudaGetSymbolAddress((void**)&us2, g_u2s);

    const int threads = 256;
    const int blocksI = (NV + threads - 1) / threads;
    dim3 grid(Wd / TX, Hd / TY, Bd);

    k_init<<<blocksI, threads>>>(x, y, t, l, us1, us2);                       // U1 -> us
    k_fused<true,  false, 0, 0><<<grid, threads>>>(t, l, a, us1, us2, ud1, ud2); // P1,U2
    k_fused<false, false, 0, 1><<<grid, threads>>>(t, l, a, ud1, ud2, us1, us2); // P2,U3
    k_fused<false, false, 1, 0><<<grid, threads>>>(t, l, a, us1, us2, ud1, ud2); // P3,U4
    k_fused<false, false, 0, 1><<<grid, threads>>>(t, l, a, ud1, ud2, us1, us2); // P4,U5
    k_fused<false, false, 1, 0><<<grid, threads>>>(t, l, a, us1, us2, ud1, ud2); // P5,U6
    k_fused<false, false, 0, 1><<<grid, threads>>>(t, l, a, ud1, ud2, us1, us2); // P6,U7
    k_fused<false, false, 1, 0><<<grid, threads>>>(t, l, a, us1, us2, ud1, ud2); // P7,U8
    k_fused<false, false, 0, 1><<<grid, threads>>>(t, l, a, ud1, ud2, us1, us2); // P8,U9
    k_fused<false, true,  1, 0><<<grid, threads>>>(t, l, a, us1, us2, ud1, ud2); // P9,U10 -> d_out
}

// round 4
// speedup vs baseline: 1.0852x; 1.0852x over previous
#include <cuda_runtime.h>

#define Wd 256
#define Hd 256
#define Bd 64
#define NPIX (Bd*Hd*Wd)
#define NV   (NPIX/4)
#define EPSf 1e-12f

#define TX 64
#define TY 16
#define S  72   // common smem row stride (floats)

// ---- iteration-invariant scratch ----
__device__ __align__(16) float g_g2x[NPIX];
__device__ __align__(16) float g_g2y[NPIX];
__device__ __align__(16) float g_rc [NPIX];
// ---- double-buffered dual state ----
__device__ __align__(16) float g_p11[2][NPIX];
__device__ __align__(16) float g_p12[2][NPIX];
__device__ __align__(16) float g_p21[2][NPIX];
__device__ __align__(16) float g_p22[2][NPIX];
// ---- u scratch (ping-pongs with d_out) ----
__device__ __align__(16) float g_u1s[NPIX];
__device__ __align__(16) float g_u2s[NPIX];

union F4 { float4 v; float f[4]; };

__device__ __forceinline__ float4 ld4(const float* p) { return *reinterpret_cast<const float4*>(p); }
__device__ __forceinline__ void   st4(float* p, float4 v) { *reinterpret_cast<float4*>(p) = v; }

// p-update lane: p' = (p + taut*grad_u) / (1 + taut*|grad_u|)
__device__ __forceinline__ void p_lane(
    float uC1, float uR1, float uD1, float uC2, float uR2, float uD2,
    bool hasR, bool hasD, float taut,
    float p11, float p12, float p21, float p22,
    float& o11, float& o12, float& o21, float& o22)
{
    float u1x = hasR ? (uR1 - uC1) : 0.f;
    float u2x = hasR ? (uR2 - uC2) : 0.f;
    float u1y = hasD ? (uD1 - uC1) : 0.f;
    float u2y = hasD ? (uD2 - uC2) : 0.f;
    float n1 = sqrtf(u1x*u1x + u1y*u1y + EPSf);
    float n2 = sqrtf(u2x*u2x + u2y*u2y + EPSf);
    float f1 = 1.0f / (1.0f + taut * n1);
    float f2 = 1.0f / (1.0f + taut * n2);
    o11 = (p11 + taut * u1x) * f1;
    o12 = (p12 + taut * u1y) * f1;
    o21 = (p21 + taut * u2x) * f2;
    o22 = (p22 + taut * u2y) * f2;
}

// u-update lane: u' = u + v(u) + ts*div(p)
__device__ __forceinline__ void u_lane(
    float u1, float u2, float gx, float gy, float rc,
    float p11, float p11L, float p12, float p12U,
    float p21, float p21L, float p22, float p22U,
    bool j0, bool i0, float ts, float l_t,
    float& o1, float& o2)
{
    float dx1 = j0 ? p11 : (p11 - p11L);
    float dx2 = j0 ? p21 : (p21 - p21L);
    float dy1 = i0 ? p12 : (p12 - p12U);
    float dy2 = i0 ? p22 : (p22 - p22U);
    float rho  = rc + gx * u1 + gy * u2 + EPSf;
    float grad = gx * gx + gy * gy + EPSf;
    float lg   = l_t * grad;
    float v1, v2;
    if      (rho < -lg)   { v1 =  l_t * gx; v2 =  l_t * gy; }
    else if (rho >  lg)   { v1 = -l_t * gx; v2 = -l_t * gy; }
    else if (grad > EPSf) { float s = -rho / grad; v1 = s * gx; v2 = s * gy; }
    else                  { v1 = 0.f; v2 = 0.f; }
    o1 = u1 + v1 + ts * (dx1 + dy1);
    o2 = u2 + v2 + ts * (dx2 + dy2);
}

// ============================================================================
// Init: g2x, g2y, rc = y - x, and iteration-1 u-update (u=0, p=0).
// ============================================================================
__global__ void __launch_bounds__(256) k_init(
    const float* __restrict__ x, const float* __restrict__ y,
    const float* __restrict__ tp, const float* __restrict__ lp,
    float* __restrict__ u1, float* __restrict__ u2)
{
    int v = blockIdx.x * blockDim.x + threadIdx.x;
    if (v >= NV) return;
    int idx = v << 2;
    int j4 = idx & (Wd - 1);
    int i  = (idx >> 8) & (Hd - 1);

    float ts  = tp[0];
    float l_t = lp[0] * ts;

    F4 X, Y, Yu, Yd, Xu, Xd;
    X.v = ld4(x + idx);
    Y.v = ld4(y + idx);
    float yl = (j4 > 0)       ? y[idx - 1] : 0.f;
    float yr = (j4 + 4 < Wd)  ? y[idx + 4] : 0.f;
    Yu.v = (i > 0)      ? ld4(y + idx - Wd) : make_float4(0,0,0,0);
    Yd.v = (i < Hd - 1) ? ld4(y + idx + Wd) : make_float4(0,0,0,0);
    Xd.v = (i == 0)      ? ld4(x + idx + Wd) : make_float4(0,0,0,0);
    Xu.v = (i == Hd - 1) ? ld4(x + idx - Wd) : make_float4(0,0,0,0);

    F4 GX, GY, RC, O1, O2;
#pragma unroll
    for (int k = 0; k < 4; k++) {
        int j = j4 + k;
        float gx;
        if (j == 0)            gx = 0.5f * (X.f[1] - X.f[0]);
        else if (j == Wd - 1)  gx = 0.5f * (X.f[3] - X.f[2]);
        else {
            float yn = (k < 3) ? Y.f[k + 1] : yr;
            float yp = (k > 0) ? Y.f[k - 1] : yl;
            gx = 0.5f * (yn - yp);
        }
        float gy;
        if (i == 0)            gy = 0.5f * (Xd.f[k] - X.f[k]);
        else if (i == Hd - 1)  gy = 0.5f * (X.f[k] - Xu.f[k]);
        else                   gy = 0.5f * (Yd.f[k] - Yu.f[k]);

        float rc = Y.f[k] - X.f[k];
        GX.f[k] = gx; GY.f[k] = gy; RC.f[k] = rc;

        float rho  = rc + EPSf;
        float grad = gx * gx + gy * gy + EPSf;
        float lg   = l_t * grad;
        float v1, v2;
        if      (rho < -lg)   { v1 =  l_t * gx; v2 =  l_t * gy; }
        else if (rho >  lg)   { v1 = -l_t * gx; v2 = -l_t * gy; }
        else if (grad > EPSf) { float s = -rho / grad; v1 = s * gx; v2 = s * gy; }
        else                  { v1 = 0.f; v2 = 0.f; }
        O1.f[k] = v1; O2.f[k] = v2;
    }
    st4(g_g2x + idx, GX.v);
    st4(g_g2y + idx, GY.v);
    st4(g_rc  + idx, RC.v);
    st4(u1 + idx, O1.v);
    st4(u2 + idx, O2.v);
}

// ============================================================================
// Double fused: (P_k, U_{k+1}, P_{k+1}, U_{k+2}) in one launch.
// smem row maps:  sU rows 0..19  <-> grow = ty0-2+r   (cols: cc <-> gcol = tx0+cc-4)
//                 sP rows 0..18  <-> grow = ty0-2+r
//                 sG rows 0..17  <-> grow = ty0-1+r
// All global loads issue in one front burst; p and u updated in place in smem.
// ============================================================================
template<bool FIRST, int PRD, int PWR>
__global__ void __launch_bounds__(256, 4) k_fused2(
    const float* __restrict__ tp, const float* __restrict__ lp,
    const float* __restrict__ ap,
    const float* __restrict__ u1r, const float* __restrict__ u2r,
    float* __restrict__ u1w, float* __restrict__ u2w)
{
    __shared__ __align__(16) float sU1[20*S], sU2[20*S];
    __shared__ __align__(16) float sP11[19*S], sP12[19*S], sP21[19*S], sP22[19*S];
    __shared__ __align__(16) float sGX[18*S], sGY[18*S], sRC[18*S];

    const int tid = threadIdx.x;
    const int tx0 = blockIdx.x * TX;
    const int ty0 = blockIdx.y * TY;
    const size_t pbase = (size_t)blockIdx.z * (Hd * Wd);

    const float ts   = tp[0];
    const float l_t  = lp[0] * ts;
    const float taut = ap[0] / ts;

    // ---- front-loaded global reads ----
    for (int t = tid; t < 20*18; t += 256) {
        int r = t / 18, v = t % 18;
        int gr = ty0 - 2 + r, gj = tx0 - 4 + 4*v;
        float4 a = make_float4(0,0,0,0), b = a;
        if (gr >= 0 && gr < Hd && gj >= 0 && gj < Wd) {
            size_t o = pbase + (size_t)gr * Wd + gj;
            a = ld4(u1r + o); b = ld4(u2r + o);
        }
        st4(sU1 + r*S + 4*v, a);
        st4(sU2 + r*S + 4*v, b);
    }
    for (int t = tid; t < 19*18; t += 256) {
        int r = t / 18, v = t % 18;
        int gr = ty0 - 2 + r, gj = tx0 - 4 + 4*v;
        float4 a = make_float4(0,0,0,0), b = a, c = a, d = a;
        if (!FIRST && gr >= 0 && gr < Hd && gj >= 0 && gj < Wd) {
            size_t o = pbase + (size_t)gr * Wd + gj;
            a = ld4(g_p11[PRD] + o); b = ld4(g_p12[PRD] + o);
            c = ld4(g_p21[PRD] + o); d = ld4(g_p22[PRD] + o);
        }
        st4(sP11 + r*S + 4*v, a);
        st4(sP12 + r*S + 4*v, b);
        st4(sP21 + r*S + 4*v, c);
        st4(sP22 + r*S + 4*v, d);
    }
    for (int t = tid; t < 18*18; t += 256) {
        int r = t / 18, v = t % 18;
        int gr = ty0 - 1 + r, gj = tx0 - 4 + 4*v;
        float4 a = make_float4(0,0,0,0), b = a, c = a;
        if (gr >= 0 && gr < Hd && gj >= 0 && gj < Wd) {
            size_t o = pbase + (size_t)gr * Wd + gj;
            a = ld4(g_g2x + o); b = ld4(g_g2y + o); c = ld4(g_rc + o);
        }
        st4(sGX + r*S + 4*v, a);
        st4(sGY + r*S + 4*v, b);
        st4(sRC + r*S + 4*v, c);
    }
    __syncthreads();

    // ---- stage a: p' = P(p, u) in place on sP (rows 0..18, vecs 0..17) ----
    for (int t = tid; t < 19*18; t += 256) {
        int ar = t / 18, av = t % 18;
        int grow = ty0 - 2 + ar;
        int gcol = tx0 - 4 + 4*av;
        int s_ = ar*S + 4*av;

        F4 U1c, U2c, U1d, U2d, P11, P12, P21, P22;
        U1c.v = *(float4*)(sU1 + s_);     U2c.v = *(float4*)(sU2 + s_);
        U1d.v = *(float4*)(sU1 + s_ + S); U2d.v = *(float4*)(sU2 + s_ + S);
        float u1rr = (av < 17) ? sU1[s_ + 4] : 0.f;
        float u2rr = (av < 17) ? sU2[s_ + 4] : 0.f;
        P11.v = *(float4*)(sP11 + s_); P12.v = *(float4*)(sP12 + s_);
        P21.v = *(float4*)(sP21 + s_); P22.v = *(float4*)(sP22 + s_);
        bool hasd = (grow < Hd - 1);

        F4 O11, O12, O21, O22;
#pragma unroll
        for (int k = 0; k < 4; k++) {
            int j = gcol + k;
            float uR1 = (k < 3) ? U1c.f[k+1] : u1rr;
            float uR2 = (k < 3) ? U2c.f[k+1] : u2rr;
            p_lane(U1c.f[k], uR1, U1d.f[k], U2c.f[k], uR2, U2d.f[k],
                   (j < Wd - 1), hasd, taut,
                   P11.f[k], P12.f[k], P21.f[k], P22.f[k],
                   O11.f[k], O12.f[k], O21.f[k], O22.f[k]);
        }
        st4(sP11 + s_, O11.v); st4(sP12 + s_, O12.v);
        st4(sP21 + s_, O21.v); st4(sP22 + s_, O22.v);
    }
    __syncthreads();

    // ---- stage b: u' = U(u, p') in place on sU (rows 1..18, vecs 0..17) ----
    for (int t = tid; t < 18*18; t += 256) {
        int br = t / 18, bv = t % 18;
        int grow = ty0 - 1 + br;
        int gcol = tx0 - 4 + 4*bv;
        int s_ = (br + 1)*S + 4*bv;   // sU and sP row index
        int sg = br*S + 4*bv;

        F4 U1, U2, P11, P12, P21, P22, P12u, P22u, GX, GY, RC, O1, O2;
        U1.v = *(float4*)(sU1 + s_); U2.v = *(float4*)(sU2 + s_);
        P11.v = *(float4*)(sP11 + s_); P12.v = *(float4*)(sP12 + s_);
        P21.v = *(float4*)(sP21 + s_); P22.v = *(float4*)(sP22 + s_);
        P12u.v = *(float4*)(sP12 + s_ - S);
        P22u.v = *(float4*)(sP22 + s_ - S);
        float p11l = (bv > 0) ? sP11[s_ - 1] : 0.f;
        float p21l = (bv > 0) ? sP21[s_ - 1] : 0.f;
        GX.v = *(float4*)(sGX + sg); GY.v = *(float4*)(sGY + sg); RC.v = *(float4*)(sRC + sg);
        bool i0 = (grow == 0);

#pragma unroll
        for (int k = 0; k < 4; k++) {
            int j = gcol + k;
            float l11 = (k > 0) ? P11.f[k-1] : p11l;
            float l21 = (k > 0) ? P21.f[k-1] : p21l;
            u_lane(U1.f[k], U2.f[k], GX.f[k], GY.f[k], RC.f[k],
                   P11.f[k], l11, P12.f[k], P12u.f[k],
                   P21.f[k], l21, P22.f[k], P22u.f[k],
                   (j == 0), i0, ts, l_t, O1.f[k], O2.f[k]);
        }
        st4(sU1 + s_, O1.v);
        st4(sU2 + s_, O2.v);
    }
    __syncthreads();

    // ---- stage c: p'' = P(p', u') in place on sP (rows 1..17, vecs 0..16);
    //      center tile stored to global p set PWR ----
    for (int t = tid; t < 17*17; t += 256) {
        int cr = t / 17, cv = t % 17;
        int grow = ty0 - 1 + cr;
        int gcol = tx0 - 4 + 4*cv;
        int s_ = (cr + 1)*S + 4*cv;

        F4 U1c, U2c, U1d, U2d, P11, P12, P21, P22;
        U1c.v = *(float4*)(sU1 + s_);     U2c.v = *(float4*)(sU2 + s_);
        U1d.v = *(float4*)(sU1 + s_ + S); U2d.v = *(float4*)(sU2 + s_ + S);
        float u1rr = sU1[s_ + 4];
        float u2rr = sU2[s_ + 4];
        P11.v = *(float4*)(sP11 + s_); P12.v = *(float4*)(sP12 + s_);
        P21.v = *(float4*)(sP21 + s_); P22.v = *(float4*)(sP22 + s_);
        bool hasd = (grow < Hd - 1);

        F4 O11, O12, O21, O22;
#pragma unroll
        for (int k = 0; k < 4; k++) {
            int j = gcol + k;
            float uR1 = (k < 3) ? U1c.f[k+1] : u1rr;
            float uR2 = (k < 3) ? U2c.f[k+1] : u2rr;
            p_lane(U1c.f[k], uR1, U1d.f[k], U2c.f[k], uR2, U2d.f[k],
                   (j < Wd - 1), hasd, taut,
                   P11.f[k], P12.f[k], P21.f[k], P22.f[k],
                   O11.f[k], O12.f[k], O21.f[k], O22.f[k]);
        }
        st4(sP11 + s_, O11.v); st4(sP12 + s_, O12.v);
        st4(sP21 + s_, O21.v); st4(sP22 + s_, O22.v);

        if (cr >= 1 && cv >= 1) {
            size_t o = pbase + (size_t)grow * Wd + gcol;
            st4(g_p11[PWR] + o, O11.v); st4(g_p12[PWR] + o, O12.v);
            st4(g_p21[PWR] + o, O21.v); st4(g_p22[PWR] + o, O22.v);
        }
    }
    __syncthreads();

    // ---- stage d: u'' on 64x16 center tile -> global ----
    {
        int r = tid >> 4, v = tid & 15;
        int grow = ty0 + r;
        int gcol = tx0 + 4*v;
        int s_ = (r + 2)*S + 4*v + 4;
        int sg = (r + 1)*S + 4*v + 4;

        F4 U1, U2, P11, P12, P21, P22, P12u, P22u, GX, GY, RC, O1, O2;
        U1.v = *(float4*)(sU1 + s_); U2.v = *(float4*)(sU2 + s_);
        P11.v = *(float4*)(sP11 + s_); P12.v = *(float4*)(sP12 + s_);
        P21.v = *(float4*)(sP21 + s_); P22.v = *(float4*)(sP22 + s_);
        P12u.v = *(float4*)(sP12 + s_ - S);
        P22u.v = *(float4*)(sP22 + s_ - S);
        float p11l = sP11[s_ - 1];
        float p21l = sP21[s_ - 1];
        GX.v = *(float4*)(sGX + sg); GY.v = *(float4*)(sGY + sg); RC.v = *(float4*)(sRC + sg);
        bool i0 = (grow == 0);

#pragma unroll
        for (int k = 0; k < 4; k++) {
            int j = gcol + k;
            float l11 = (k > 0) ? P11.f[k-1] : p11l;
            float l21 = (k > 0) ? P21.f[k-1] : p21l;
            u_lane(U1.f[k], U2.f[k], GX.f[k], GY.f[k], RC.f[k],
                   P11.f[k], l11, P12.f[k], P12u.f[k],
                   P21.f[k], l21, P22.f[k], P22u.f[k],
                   (j == 0), i0, ts, l_t, O1.f[k], O2.f[k]);
        }
        size_t o = pbase + (size_t)grow * Wd + gcol;
        st4(u1w + o, O1.v);
        st4(u2w + o, O2.v);
    }
}

// ============================================================================
// Final single fused: (P9, U10). No p store. Front-loaded loads, in-place smem.
// sU rows 0..17 <-> grow ty0-1+r; sP rows 0..16 <-> grow ty0-1+r; sG rows 0..15 <-> ty0+r.
// ============================================================================
template<int PRD>
__global__ void __launch_bounds__(256, 4) k_fused1(
    const float* __restrict__ tp, const float* __restrict__ lp,
    const float* __restrict__ ap,
    const float* __restrict__ u1r, const float* __restrict__ u2r,
    float* __restrict__ u1w, float* __restrict__ u2w)
{
    __shared__ __align__(16) float sU1[18*S], sU2[18*S];
    __shared__ __align__(16) float sP11[17*S], sP12[17*S], sP21[17*S], sP22[17*S];
    __shared__ __align__(16) float sGX[16*S], sGY[16*S], sRC[16*S];

    const int tid = threadIdx.x;
    const int tx0 = blockIdx.x * TX;
    const int ty0 = blockIdx.y * TY;
    const size_t pbase = (size_t)blockIdx.z * (Hd * Wd);

    const float ts   = tp[0];
    const float l_t  = lp[0] * ts;
    const float taut = ap[0] / ts;

    // ---- front-loaded global reads ----
    for (int t = tid; t < 18*18; t += 256) {
        int r = t / 18, v = t % 18;
        int gr = ty0 - 1 + r, gj = tx0 - 4 + 4*v;
        float4 a = make_float4(0,0,0,0), b = a;
        if (gr >= 0 && gr < Hd && gj >= 0 && gj < Wd) {
            size_t o = pbase + (size_t)gr * Wd + gj;
            a = ld4(u1r + o); b = ld4(u2r + o);
        }
        st4(sU1 + r*S + 4*v, a);
        st4(sU2 + r*S + 4*v, b);
    }
    for (int t = tid; t < 17*17; t += 256) {
        int r = t / 17, v = t % 17;
        int gr = ty0 - 1 + r, gj = tx0 - 4 + 4*v;
        float4 a = make_float4(0,0,0,0), b = a, c = a, d = a;
        if (gr >= 0 && gr < Hd && gj >= 0 && gj < Wd) {
            size_t o = pbase + (size_t)gr * Wd + gj;
            a = ld4(g_p11[PRD] + o); b = ld4(g_p12[PRD] + o);
            c = ld4(g_p21[PRD] + o); d = ld4(g_p22[PRD] + o);
        }
        st4(sP11 + r*S + 4*v, a);
        st4(sP12 + r*S + 4*v, b);
        st4(sP21 + r*S + 4*v, c);
        st4(sP22 + r*S + 4*v, d);
    }
    for (int t = tid; t < 16*16; t += 256) {
        int r = t / 16, v = t % 16;
        int gr = ty0 + r, gj = tx0 + 4*v;
        size_t o = pbase + (size_t)gr * Wd + gj;
        st4(sGX + r*S + 4*v + 4, ld4(g_g2x + o));
        st4(sGY + r*S + 4*v + 4, ld4(g_g2y + o));
        st4(sRC + r*S + 4*v + 4, ld4(g_rc + o));
    }
    __syncthreads();

    // ---- p' = P9 in place on sP (17 rows x 17 vecs) ----
    for (int t = tid; t < 17*17; t += 256) {
        int pr = t / 17, pv = t % 17;
        int grow = ty0 - 1 + pr;
        int gcol = tx0 - 4 + 4*pv;
        int s_ = pr*S + 4*pv;

        F4 U1c, U2c, U1d, U2d, P11, P12, P21, P22;
        U1c.v = *(float4*)(sU1 + s_);     U2c.v = *(float4*)(sU2 + s_);
        U1d.v = *(float4*)(sU1 + s_ + S); U2d.v = *(float4*)(sU2 + s_ + S);
        float u1rr = sU1[s_ + 4];
        float u2rr = sU2[s_ + 4];
        P11.v = *(float4*)(sP11 + s_); P12.v = *(float4*)(sP12 + s_);
        P21.v = *(float4*)(sP21 + s_); P22.v = *(float4*)(sP22 + s_);
        bool hasd = (grow < Hd - 1);

        F4 O11, O12, O21, O22;
#pragma unroll
        for (int k = 0; k < 4; k++) {
            int j = gcol + k;
            float uR1 = (k < 3) ? U1c.f[k+1] : u1rr;
            float uR2 = (k < 3) ? U2c.f[k+1] : u2rr;
            p_lane(U1c.f[k], uR1, U1d.f[k], U2c.f[k], uR2, U2d.f[k],
                   (j < Wd - 1), hasd, taut,
                   P11.f[k], P12.f[k], P21.f[k], P22.f[k],
                   O11.f[k], O12.f[k], O21.f[k], O22.f[k]);
        }
        st4(sP11 + s_, O11.v); st4(sP12 + s_, O12.v);
        st4(sP21 + s_, O21.v); st4(sP22 + s_, O22.v);
    }
    __syncthreads();

    // ---- u'' = U10 on center tile -> d_out ----
    {
        int r = tid >> 4, v = tid & 15;
        int grow = ty0 + r;
        int gcol = tx0 + 4*v;
        int s_ = (r + 1)*S + 4*v + 4;
        int sg = r*S + 4*v + 4;

        F4 U1, U2, P11, P12, P21, P22, P12u, P22u, GX, GY, RC, O1, O2;
        U1.v = *(float4*)(sU1 + s_); U2.v = *(float4*)(sU2 + s_);
        P11.v = *(float4*)(sP11 + s_); P12.v = *(float4*)(sP12 + s_);
        P21.v = *(float4*)(sP21 + s_); P22.v = *(float4*)(sP22 + s_);
        P12u.v = *(float4*)(sP12 + s_ - S);
        P22u.v = *(float4*)(sP22 + s_ - S);
        float p11l = sP11[s_ - 1];
        float p21l = sP21[s_ - 1];
        GX.v = *(float4*)(sGX + sg); GY.v = *(float4*)(sGY + sg); RC.v = *(float4*)(sRC + sg);
        bool i0 = (grow == 0);

#pragma unroll
        for (int k = 0; k < 4; k++) {
            int j = gcol + k;
            float l11 = (k > 0) ? P11.f[k-1] : p11l;
            float l21 = (k > 0) ? P21.f[k-1] : p21l;
            u_lane(U1.f[k], U2.f[k], GX.f[k], GY.f[k], RC.f[k],
                   P11.f[k], l11, P12.f[k], P12u.f[k],
                   P21.f[k], l21, P22.f[k], P22u.f[k],
                   (j == 0), i0, ts, l_t, O1.f[k], O2.f[k]);
        }
        size_t o = pbase + (size_t)grow * Wd + gcol;
        st4(u1w + o, O1.v);
        st4(u2w + o, O2.v);
    }
}

// ============================================================================
// Schedule: init(U1)->us; 4x double fused; 1x single fused -> d_out.
// ============================================================================
extern "C" void kernel_launch(void* const* d_in, const int* in_sizes, int n_in,
                              void* d_out, int out_size)
{
    const float* x = (const float*)d_in[0];
    const float* y = (const float*)d_in[1];
    const float* t = (const float*)d_in[8];
    const float* l = (const float*)d_in[9];
    const float* a = (const float*)d_in[10];

    float* ud1 = (float*)d_out;
    float* ud2 = ud1 + NPIX;

    float* us1; cudaGetSymbolAddress((void**)&us1, g_u1s);
    float* us2; cudaGetSymbolAddress((void**)&us2, g_u2s);

    const int threads = 256;
    const int blocksI = (NV + threads - 1) / threads;
    dim3 grid(Wd / TX, Hd / TY, Bd);

    k_init<<<blocksI, threads>>>(x, y, t, l, us1, us2);                           // U1 -> us
    k_fused2<true,  0, 0><<<grid, threads>>>(t, l, a, us1, us2, ud1, ud2);        // P1,U2,P2,U3
    k_fused2<false, 0, 1><<<grid, threads>>>(t, l, a, ud1, ud2, us1, us2);        // P3,U4,P4,U5
    k_fused2<false, 1, 0><<<grid, threads>>>(t, l, a, us1, us2, ud1, ud2);        // P5,U6,P6,U7
    k_fused2<false, 0, 1><<<grid, threads>>>(t, l, a, ud1, ud2, us1, us2);        // P7,U8,P8,U9
    k_fused1<1><<<grid, threads>>>(t, l, a, us1, us2, ud1, ud2);                  // P9,U10 -> d_out
}

// round 5
// speedup vs baseline: 1.4750x; 1.3592x over previous
#include <cuda_runtime.h>

#define Wd 256
#define Hd 256
#define Bd 64
#define NPIX (Bd*Hd*Wd)
#define HPIX (NPIX/2)      // elements per batch half
#define NVH  (HPIX/4)      // float4 vectors per half
#define EPSf 1e-12f

// ---- iteration-invariant + dual-state scratch ----
__device__ __align__(16) float g_g2x[NPIX];
__device__ __align__(16) float g_g2y[NPIX];
__device__ __align__(16) float g_rc [NPIX];
__device__ __align__(16) float g_p11[NPIX];
__device__ __align__(16) float g_p12[NPIX];
__device__ __align__(16) float g_p21[NPIX];
__device__ __align__(16) float g_p22[NPIX];

union F4 { float4 v; float f[4]; };

__device__ __forceinline__ float4 ld4(const float* p) { return *reinterpret_cast<const float4*>(p); }
__device__ __forceinline__ void   st4(float* p, float4 v) { *reinterpret_cast<float4*>(p) = v; }

// ============================================================================
// Init (per half): g2x, g2y, rc = y-x, iteration-1 u (u=0, p=0).
// ============================================================================
__global__ void __launch_bounds__(256) k_init(
    const float* __restrict__ x, const float* __restrict__ y,
    const float* __restrict__ tp, const float* __restrict__ lp,
    float* __restrict__ u1, float* __restrict__ u2, int off)
{
    int v = blockIdx.x * blockDim.x + threadIdx.x;
    if (v >= NVH) return;
    int il = v << 2;            // local index within half (image-aligned)
    int idx = il + off;
    int j4 = il & (Wd - 1);
    int i  = (il >> 8) & (Hd - 1);

    float ts  = tp[0];
    float l_t = lp[0] * ts;

    F4 X, Y, Yu, Yd, Xu, Xd;
    X.v = ld4(x + idx);
    Y.v = ld4(y + idx);
    float yl = (j4 > 0)       ? y[idx - 1] : 0.f;
    float yr = (j4 + 4 < Wd)  ? y[idx + 4] : 0.f;
    Yu.v = (i > 0)      ? ld4(y + idx - Wd) : make_float4(0,0,0,0);
    Yd.v = (i < Hd - 1) ? ld4(y + idx + Wd) : make_float4(0,0,0,0);
    Xd.v = (i == 0)      ? ld4(x + idx + Wd) : make_float4(0,0,0,0);
    Xu.v = (i == Hd - 1) ? ld4(x + idx - Wd) : make_float4(0,0,0,0);

    F4 GX, GY, RC, O1, O2;
#pragma unroll
    for (int k = 0; k < 4; k++) {
        int j = j4 + k;
        float gx;
        if (j == 0)            gx = 0.5f * (X.f[1] - X.f[0]);
        else if (j == Wd - 1)  gx = 0.5f * (X.f[3] - X.f[2]);
        else {
            float yn = (k < 3) ? Y.f[k + 1] : yr;
            float yp = (k > 0) ? Y.f[k - 1] : yl;
            gx = 0.5f * (yn - yp);
        }
        float gy;
        if (i == 0)            gy = 0.5f * (Xd.f[k] - X.f[k]);
        else if (i == Hd - 1)  gy = 0.5f * (X.f[k] - Xu.f[k]);
        else                   gy = 0.5f * (Yd.f[k] - Yu.f[k]);

        float rc = Y.f[k] - X.f[k];
        GX.f[k] = gx; GY.f[k] = gy; RC.f[k] = rc;

        float rho  = rc + EPSf;
        float grad = gx * gx + gy * gy + EPSf;
        float lg   = l_t * grad;
        float v1, v2;
        if      (rho < -lg)   { v1 =  l_t * gx; v2 =  l_t * gy; }
        else if (rho >  lg)   { v1 = -l_t * gx; v2 = -l_t * gy; }
        else if (grad > EPSf) { float s = -rho / grad; v1 = s * gx; v2 = s * gy; }
        else                  { v1 = 0.f; v2 = 0.f; }
        O1.f[k] = v1; O2.f[k] = v2;
    }
    st4(g_g2x + idx, GX.v);
    st4(g_g2y + idx, GY.v);
    st4(g_rc  + idx, RC.v);
    st4(u1 + idx, O1.v);
    st4(u2 + idx, O2.v);
}

// ============================================================================
// P update (per half): forward grads of u, dual projection. In-place p.
// ============================================================================
template <bool FIRST>
__global__ void __launch_bounds__(256) k_update_p(
    const float* __restrict__ tp, const float* __restrict__ ap,
    const float* __restrict__ u1, const float* __restrict__ u2, int off)
{
    int v = blockIdx.x * blockDim.x + threadIdx.x;
    if (v >= NVH) return;
    int il = v << 2;
    int idx = il + off;
    int j4 = il & (Wd - 1);
    int i  = (il >> 8) & (Hd - 1);

    float taut = ap[0] / tp[0];

    F4 U1, U2, U1d, U2d;
    U1.v = ld4(u1 + idx);
    U2.v = ld4(u2 + idx);
    float u1r = (j4 + 4 < Wd) ? u1[idx + 4] : 0.f;
    float u2r = (j4 + 4 < Wd) ? u2[idx + 4] : 0.f;
    bool has_down = (i < Hd - 1);
    U1d.v = has_down ? ld4(u1 + idx + Wd) : make_float4(0,0,0,0);
    U2d.v = has_down ? ld4(u2 + idx + Wd) : make_float4(0,0,0,0);

    F4 P11, P12, P21, P22;
    if (!FIRST) {
        P11.v = ld4(g_p11 + idx);
        P12.v = ld4(g_p12 + idx);
        P21.v = ld4(g_p21 + idx);
        P22.v = ld4(g_p22 + idx);
    }

    F4 O11, O12, O21, O22;
#pragma unroll
    for (int k = 0; k < 4; k++) {
        int j = j4 + k;
        float u1x = (j < Wd - 1) ? ((k < 3) ? U1.f[k + 1] : u1r) - U1.f[k] : 0.f;
        float u2x = (j < Wd - 1) ? ((k < 3) ? U2.f[k + 1] : u2r) - U2.f[k] : 0.f;
        float u1y = has_down ? (U1d.f[k] - U1.f[k]) : 0.f;
        float u2y = has_down ? (U2d.f[k] - U2.f[k]) : 0.f;

        float n1 = sqrtf(u1x * u1x + u1y * u1y + EPSf);
        float n2 = sqrtf(u2x * u2x + u2y * u2y + EPSf);
        float f1 = 1.0f / (1.0f + taut * n1);
        float f2 = 1.0f / (1.0f + taut * n2);

        float p11o = FIRST ? 0.f : P11.f[k];
        float p12o = FIRST ? 0.f : P12.f[k];
        float p21o = FIRST ? 0.f : P21.f[k];
        float p22o = FIRST ? 0.f : P22.f[k];

        O11.f[k] = (p11o + taut * u1x) * f1;
        O12.f[k] = (p12o + taut * u1y) * f1;
        O21.f[k] = (p21o + taut * u2x) * f2;
        O22.f[k] = (p22o + taut * u2y) * f2;
    }
    st4(g_p11 + idx, O11.v);
    st4(g_p12 + idx, O12.v);
    st4(g_p21 + idx, O21.v);
    st4(g_p22 + idx, O22.v);
}

// ============================================================================
// U update (per half): thresholding + u = v + ts * div(p). In-place u.
// ============================================================================
__global__ void __launch_bounds__(256) k_update_u(
    const float* __restrict__ tp, const float* __restrict__ lp,
    float* __restrict__ u1, float* __restrict__ u2, int off)
{
    int v = blockIdx.x * blockDim.x + threadIdx.x;
    if (v >= NVH) return;
    int il = v << 2;
    int idx = il + off;
    int j4 = il & (Wd - 1);
    int i  = (il >> 8) & (Hd - 1);

    float ts  = tp[0];
    float l_t = lp[0] * ts;

    F4 U1, U2, GX, GY, RC, P11, P12, P21, P22, P12u, P22u;
    U1.v  = ld4(u1 + idx);
    U2.v  = ld4(u2 + idx);
    GX.v  = ld4(g_g2x + idx);
    GY.v  = ld4(g_g2y + idx);
    RC.v  = ld4(g_rc + idx);
    P11.v = ld4(g_p11 + idx);
    P12.v = ld4(g_p12 + idx);
    P21.v = ld4(g_p21 + idx);
    P22.v = ld4(g_p22 + idx);
    float p11l = (j4 > 0) ? g_p11[idx - 1] : 0.f;
    float p21l = (j4 > 0) ? g_p21[idx - 1] : 0.f;
    bool has_up = (i > 0);
    P12u.v = has_up ? ld4(g_p12 + idx - Wd) : make_float4(0,0,0,0);
    P22u.v = has_up ? ld4(g_p22 + idx - Wd) : make_float4(0,0,0,0);

    F4 O1, O2;
#pragma unroll
    for (int k = 0; k < 4; k++) {
        int j = j4 + k;
        float lft11 = (k > 0) ? P11.f[k - 1] : p11l;
        float lft21 = (k > 0) ? P21.f[k - 1] : p21l;
        float dx1 = (j == 0) ? P11.f[k] : (P11.f[k] - lft11);
        float dx2 = (j == 0) ? P21.f[k] : (P21.f[k] - lft21);
        float dy1 = has_up ? (P12.f[k] - P12u.f[k]) : P12.f[k];
        float dy2 = has_up ? (P22.f[k] - P22u.f[k]) : P22.f[k];

        float gx = GX.f[k], gy = GY.f[k];
        float rho  = RC.f[k] + gx * U1.f[k] + gy * U2.f[k] + EPSf;
        float grad = gx * gx + gy * gy + EPSf;
        float lg   = l_t * grad;
        float v1, v2;
        if      (rho < -lg)   { v1 =  l_t * gx; v2 =  l_t * gy; }
        else if (rho >  lg)   { v1 = -l_t * gx; v2 = -l_t * gy; }
        else if (grad > EPSf) { float s = -rho / grad; v1 = s * gx; v2 = s * gy; }
        else                  { v1 = 0.f; v2 = 0.f; }

        O1.f[k] = U1.f[k] + v1 + ts * (dx1 + dy1);
        O2.f[k] = U2.f[k] + v2 + ts * (dx2 + dy2);
    }
    st4(u1 + idx, O1.v);
    st4(u2 + idx, O2.v);
}

// ============================================================================
// Launch: run the full pipeline on batch half 0 (images 0..31), then half 1.
// Per-half working set (u 16MB + p 32MB + g 24MB = 72MB) stays L2-resident
// across the half's 19 launches.
// ============================================================================
extern "C" void kernel_launch(void* const* d_in, const int* in_sizes, int n_in,
                              void* d_out, int out_size)
{
    const float* x = (const float*)d_in[0];
    const float* y = (const float*)d_in[1];
    const float* t = (const float*)d_in[8];
    const float* l = (const float*)d_in[9];
    const float* a = (const float*)d_in[10];

    float* u1 = (float*)d_out;
    float* u2 = u1 + NPIX;

    const int threads = 256;
    const int blocks  = (NVH + threads - 1) / threads;

    for (int h = 0; h < 2; ++h) {
        int off = h * HPIX;
        k_init<<<blocks, threads>>>(x, y, t, l, u1, u2, off);
        k_update_p<true><<<blocks, threads>>>(t, a, u1, u2, off);
        for (int it = 0; it < 9; ++it) {
            k_update_u<<<blocks, threads>>>(t, l, u1, u2, off);
            if (it < 8)
                k_update_p<false><<<blocks, threads>>>(t, a, u1, u2, off);
        }
    }
}